// round 17
// baseline (speedup 1.0000x reference)
#include <cuda_runtime.h>
#include <cuda_bf16.h>
#include <math.h>

#define NN 100000
#define EE 1600000
#define HH 128
#define GG 64
#define SCAN_BLKS 100
#define SCAN_NPB 1000

// ---------- device scratch ----------
__device__ int   g_degcnt[NN];
__device__ float g_dinv[NN];
__device__ int   g_rowptr[NN + 1];
__device__ int   g_cursor[NN];
__device__ int   g_colsrc[EE];
__device__ int   g_bsum[SCAN_BLKS];
__device__ __align__(16) __nv_bfloat16 g_bufA[(size_t)(NN + 1) * HH];  // +1 dummy zero row
__device__ __align__(16) __nv_bfloat16 g_bufB[(size_t)(NN + 1) * HH];
__device__ __align__(16) __nv_bfloat16 g_whi[3][HH * HH];   // Wt[n][k] bf16
__device__ float g_sums[GG * HH];
__device__ int   g_cnt[GG];

// ---------- helpers ----------
__device__ __forceinline__ float2 bf2f(unsigned int v) {
    __nv_bfloat162 b = *reinterpret_cast<__nv_bfloat162*>(&v);
    return __bfloat1622float2(b);
}
__device__ __forceinline__ unsigned int f2bf(float a, float b) {
    __nv_bfloat162 r = __float22bfloat162_rn(make_float2(a, b));
    return *reinterpret_cast<unsigned int*>(&r);
}
__device__ __forceinline__ float elu_f(float x) { return x > 0.f ? x : expm1f(x); }

// ---------- CSR chain (stream 2) ----------
__global__ void k_zdeg() {
    int i = blockIdx.x * blockDim.x + threadIdx.x;
    if (i < NN) g_degcnt[i] = 0;
}

__global__ void k_hist(const int* __restrict__ dst) {
    int i = blockIdx.x * 256 + threadIdx.x;
    if (i < EE) atomicAdd(&g_degcnt[dst[i]], 1);
}

__global__ void k_scan1() {
    __shared__ int sm[256];
    int blk = blockIdx.x, tid = threadIdx.x;
    int base = blk * SCAN_NPB;
    int s = 0;
    for (int i = tid; i < SCAN_NPB; i += 256) {
        int n = base + i;
        if (n < NN) s += g_degcnt[n];
    }
    sm[tid] = s;
    __syncthreads();
    for (int off = 128; off > 0; off >>= 1) {
        if (tid < off) sm[tid] += sm[tid + off];
        __syncthreads();
    }
    if (tid == 0) g_bsum[blk] = sm[0];
}

// scan3 with inline scan of block sums
__global__ void k_scan3() {
    __shared__ int sm[256];
    __shared__ int sbase;
    int blk = blockIdx.x, tid = threadIdx.x;
    int base = blk * SCAN_NPB;

    if (tid == 0) {
        int run = 0;
        for (int i = 0; i < blk; i++) run += g_bsum[i];
        sbase = run;
    }

    const int chunk = 4;
    int start = base + tid * chunk;
    int s = 0;
#pragma unroll
    for (int j = 0; j < chunk; j++) {
        int n = start + j;
        if (n < base + SCAN_NPB && n < NN) s += g_degcnt[n];
    }
    sm[tid] = s;
    __syncthreads();
    for (int off = 1; off < 256; off <<= 1) {
        int v = 0;
        if (tid >= off) v = sm[tid - off];
        __syncthreads();
        sm[tid] += v;
        __syncthreads();
    }
    int run = sbase + sm[tid] - s;
#pragma unroll
    for (int j = 0; j < chunk; j++) {
        int n = start + j;
        if (n < base + SCAN_NPB && n < NN) {
            int d = g_degcnt[n];
            g_rowptr[n] = run;
            g_cursor[n] = run;
            g_dinv[n] = rsqrtf((float)(d + 1));
            run += d;
        }
    }
    if (blk == SCAN_BLKS - 1 && tid == 255) g_rowptr[NN] = sbase + sm[255];
}

__global__ void k_fill(const int* __restrict__ src, const int* __restrict__ dst) {
    int i = blockIdx.x * 256 + threadIdx.x;
    if (i < EE) {
        int d = dst[i];
        int pos = atomicAdd(&g_cursor[d], 1);
        g_colsrc[pos] = src[i];
    }
}

// ---------- feature chain (main stream) ----------
__global__ void k_init_misc() {
    int i = blockIdx.x * blockDim.x + threadIdx.x;
    int stride = gridDim.x * blockDim.x;
    for (int j = i; j < GG * HH; j += stride) g_sums[j] = 0.f;
    for (int j = i; j < GG; j += stride) g_cnt[j] = 0;
    for (int j = i; j < HH; j += stride) {
        g_bufA[(size_t)NN * HH + j] = __float2bfloat16(0.f);
        g_bufB[(size_t)NN * HH + j] = __float2bfloat16(0.f);
    }
}

__global__ void k_prepw(const float* __restrict__ W1, const float* __restrict__ W2,
                        const float* __restrict__ W3) {
    int i = blockIdx.x * 256 + threadIdx.x;
    if (i >= 3 * HH * HH) return;
    int w = i / (HH * HH);
    int j = i % (HH * HH);
    int n = j >> 7, k = j & 127;
    const float* Wp = (w == 0) ? W1 : (w == 1) ? W2 : W3;
    g_whi[w][n * HH + k] = __float2bfloat16(Wp[k * HH + n]);
}

// ---------- HMMA GEMM core ----------
#define ROWB 272
#define SM_WH 34816
#define GT_SMEM 69632

#define GEMM_BODY                                                                      \
    unsigned int sb;                                                                   \
    asm("{ .reg .u64 t; cvta.to.shared.u64 t, %1; cvt.u32.u64 %0, t; }"                \
        : "=r"(sb) : "l"(smem));                                                       \
    const int R = wid * 16;                                                            \
    float acc[16][4];                                                                  \
    _Pragma("unroll") for (int nb = 0; nb < 16; nb++)                                  \
        _Pragma("unroll") for (int j = 0; j < 4; j++) acc[nb][j] = 0.f;                \
    unsigned int aBase = sb + (R + (lane & 15)) * ROWB + (lane >> 4) * 16;             \
    unsigned int bRow = (lane & 7) * ROWB + ((lane >> 3) & 1) * 16;                    \
    unsigned int bhBase = sb + SM_WH + bRow;                                           \
    _Pragma("unroll") for (int ks = 0; ks < 8; ks++) {                                 \
        unsigned int a0, a1, a2, a3;                                                   \
        asm volatile("ldmatrix.sync.aligned.m8n8.x4.shared.b16 {%0,%1,%2,%3}, [%4];"   \
                     : "=r"(a0), "=r"(a1), "=r"(a2), "=r"(a3)                          \
                     : "r"(aBase + ks * 32));                                          \
        _Pragma("unroll") for (int nb = 0; nb < 16; nb++) {                            \
            unsigned int b0, b1;                                                       \
            asm volatile("ldmatrix.sync.aligned.m8n8.x2.shared.b16 {%0,%1}, [%2];"     \
                         : "=r"(b0), "=r"(b1)                                          \
                         : "r"(bhBase + nb * (8 * ROWB) + ks * 32));                   \
            asm volatile("mma.sync.aligned.m16n8k16.row.col.f32.bf16.bf16.f32 "        \
                         "{%0,%1,%2,%3}, {%4,%5,%6,%7}, {%8,%9}, {%0,%1,%2,%3};"       \
                         : "+f"(acc[nb][0]), "+f"(acc[nb][1]),                         \
                           "+f"(acc[nb][2]), "+f"(acc[nb][3])                          \
                         : "r"(a0), "r"(a1), "r"(a2), "r"(a3), "r"(b0), "r"(b1));      \
        }                                                                              \
    }                                                                                  \
    int r0 = rowBase + R + (lane >> 2);                                                \
    int r1 = r0 + 8;                                                                   \
    float d0 = (r0 < NN) ? g_dinv[r0] : 0.f;                                           \
    float d1 = (r1 < NN) ? g_dinv[r1] : 0.f;                                           \
    unsigned int colHalf = (lane & 3) * 2;                                             \
    _Pragma("unroll") for (int nb = 0; nb < 16; nb++) {                                \
        unsigned int c = nb * 8 + colHalf;                                             \
        if (r0 < NN)                                                                   \
            *(unsigned int*)&out[(size_t)r0 * HH + c] =                                \
                f2bf(acc[nb][0] * d0, acc[nb][1] * d0);                                \
        if (r1 < NN)                                                                   \
            *(unsigned int*)&out[(size_t)r1 * HH + c] =                                \
                f2bf(acc[nb][2] * d1, acc[nb][3] * d1);                                \
    }

// layer-1 GEMM: reads fp32 x, converts while staging
__global__ void __launch_bounds__(256) k_gemm_x(const float* __restrict__ X,
                                                const __nv_bfloat16* __restrict__ Whi,
                                                __nv_bfloat16* __restrict__ out) {
    extern __shared__ char smem[];
    const int tid = threadIdx.x;
    const int wid = tid >> 5;
    const int lane = tid & 31;
    const int rowBase = blockIdx.x * 128;

    const float4* Xg = (const float4*)X;
    const uint4* Wh = (const uint4*)Whi;
    for (int i = tid; i < 2048; i += 256) {
        int r = i >> 4, c = i & 15;
        int gr = rowBase + r;
        float4 u = make_float4(0.f, 0.f, 0.f, 0.f), v = u;
        if (gr < NN) {
            u = Xg[(size_t)gr * 32 + c * 2];
            v = Xg[(size_t)gr * 32 + c * 2 + 1];
        }
        uint4 st;
        st.x = f2bf(u.x, u.y); st.y = f2bf(u.z, u.w);
        st.z = f2bf(v.x, v.y); st.w = f2bf(v.z, v.w);
        *(uint4*)(smem + r * ROWB + c * 16) = st;
        *(uint4*)(smem + SM_WH + r * ROWB + c * 16) = Wh[i];
    }
    __syncthreads();
    GEMM_BODY
}

// ---------- fused agg + GEMM: block aggregates its 128 rows into smem, then MMA ----------
__global__ void __launch_bounds__(256) k_fused(const __nv_bfloat16* __restrict__ hs,
                                               const float* __restrict__ b,
                                               const __nv_bfloat16* __restrict__ Whi,
                                               __nv_bfloat16* __restrict__ out) {
    extern __shared__ char smem[];
    const int tid = threadIdx.x;
    const int wid = tid >> 5;
    const int lane = tid & 31;
    const int rowBase = blockIdx.x * 128;

    // stage W (no sync needed until MMA)
    const uint4* Wh = (const uint4*)Whi;
    for (int i = tid; i < 2048; i += 256)
        *(uint4*)(smem + SM_WH + (i >> 4) * ROWB + (i & 15) * 16) = Wh[i];

    // aggregate 16 nodes per warp, write bf16 rows into smem A region
    const uint2* hs2 = (const uint2*)hs;
    float4 bb = ((const float4*)b)[lane];
    for (int t = 0; t < 16; t++) {
        int lrow = wid * 16 + t;
        int node = rowBase + lrow;
        uint2 pk = make_uint2(0u, 0u);
        if (node < NN) {
            uint2 sv = hs2[(size_t)node * 32 + lane];
            float2 s0 = bf2f(sv.x), s1 = bf2f(sv.y);
            float4 acc = make_float4(s0.x, s0.y, s1.x, s1.y);
            int e = g_rowptr[node];
            int end = g_rowptr[node + 1];
            for (; e < end; e += 16) {
                int idx[16];
#pragma unroll
                for (int j = 0; j < 16; j++)
                    idx[j] = (e + j < end) ? g_colsrc[e + j] : NN;
                uint2 v[16];
#pragma unroll
                for (int j = 0; j < 16; j++)
                    v[j] = hs2[(size_t)idx[j] * 32 + lane];
#pragma unroll
                for (int j = 0; j < 16; j += 4) {
                    float2 a0 = bf2f(v[j + 0].x), c0 = bf2f(v[j + 0].y);
                    float2 a1 = bf2f(v[j + 1].x), c1 = bf2f(v[j + 1].y);
                    float2 a2 = bf2f(v[j + 2].x), c2 = bf2f(v[j + 2].y);
                    float2 a3 = bf2f(v[j + 3].x), c3 = bf2f(v[j + 3].y);
                    acc.x += (a0.x + a1.x) + (a2.x + a3.x);
                    acc.y += (a0.y + a1.y) + (a2.y + a3.y);
                    acc.z += (c0.x + c1.x) + (c2.x + c3.x);
                    acc.w += (c0.y + c1.y) + (c2.y + c3.y);
                }
            }
            float di = g_dinv[node];
            pk.x = f2bf(elu_f(acc.x * di + bb.x), elu_f(acc.y * di + bb.y));
            pk.y = f2bf(elu_f(acc.z * di + bb.z), elu_f(acc.w * di + bb.w));
        }
        *(uint2*)(smem + lrow * ROWB + lane * 8) = pk;
    }
    __syncthreads();
    GEMM_BODY
}

// ---------- standalone aggregation (layer 3) ----------
__global__ void __launch_bounds__(256) k_agg(const __nv_bfloat16* __restrict__ hs,
                                             const float* __restrict__ b,
                                             __nv_bfloat16* __restrict__ out) {
    int warp = (blockIdx.x * blockDim.x + threadIdx.x) >> 5;
    int lane = threadIdx.x & 31;
    if (warp >= NN) return;
    const uint2* hs2 = (const uint2*)hs;

    uint2 sv = hs2[(size_t)warp * 32 + lane];
    float2 s0 = bf2f(sv.x), s1 = bf2f(sv.y);
    float4 acc = make_float4(s0.x, s0.y, s1.x, s1.y);

    int e = g_rowptr[warp];
    int end = g_rowptr[warp + 1];
    for (; e < end; e += 16) {
        int idx[16];
#pragma unroll
        for (int j = 0; j < 16; j++)
            idx[j] = (e + j < end) ? g_colsrc[e + j] : NN;
        uint2 v[16];
#pragma unroll
        for (int j = 0; j < 16; j++)
            v[j] = hs2[(size_t)idx[j] * 32 + lane];
#pragma unroll
        for (int j = 0; j < 16; j += 4) {
            float2 a0 = bf2f(v[j + 0].x), c0 = bf2f(v[j + 0].y);
            float2 a1 = bf2f(v[j + 1].x), c1 = bf2f(v[j + 1].y);
            float2 a2 = bf2f(v[j + 2].x), c2 = bf2f(v[j + 2].y);
            float2 a3 = bf2f(v[j + 3].x), c3 = bf2f(v[j + 3].y);
            acc.x += (a0.x + a1.x) + (a2.x + a3.x);
            acc.y += (a0.y + a1.y) + (a2.y + a3.y);
            acc.z += (c0.x + c1.x) + (c2.x + c3.x);
            acc.w += (c0.y + c1.y) + (c2.y + c3.y);
        }
    }

    float di = g_dinv[warp];
    float4 bb = ((const float4*)b)[lane];
    uint2 st;
    st.x = f2bf(elu_f(acc.x * di + bb.x), elu_f(acc.y * di + bb.y));
    st.y = f2bf(elu_f(acc.z * di + bb.z), elu_f(acc.w * di + bb.w));
    ((uint2*)out)[(size_t)warp * 32 + lane] = st;
}

// ---------- mean-pool ----------
#define POOL_NPB 256
__global__ void k_pool(const __nv_bfloat16* __restrict__ act, const int* __restrict__ batch) {
    int col = threadIdx.x;
    int start = blockIdx.x * POOL_NPB;
    if (start >= NN) return;
    int end = min(start + POOL_NPB, NN);
    float acc = 0.f;
    int cur = batch[start];
    int cl = 0;
    for (int i = start; i < end; i++) {
        int bb = batch[i];
        if (bb != cur) {
            atomicAdd(&g_sums[cur * HH + col], acc);
            if (col == 0) atomicAdd(&g_cnt[cur], cl);
            acc = 0.f; cl = 0; cur = bb;
        }
        acc += __bfloat162float(act[(size_t)i * HH + col]);
        cl++;
    }
    atomicAdd(&g_sums[cur * HH + col], acc);
    if (col == 0) atomicAdd(&g_cnt[cur], cl);
}

// ---------- classifier head ----------
__global__ void k_mlp(const float* __restrict__ Wc1, const float* __restrict__ bc1,
                      const float* __restrict__ Wc2, const float* __restrict__ bc2,
                      float* __restrict__ out) {
    __shared__ float gs[GG][129];
    int tid = threadIdx.x;
    for (int idx = tid; idx < GG * HH; idx += 256) {
        int g = idx >> 7, k = idx & 127;
        float c = fmaxf((float)g_cnt[g], 1.f);
        gs[g][k] = g_sums[idx] / c;
    }
    __syncthreads();
    int gid = tid >> 2;
    int q = tid & 3;
    float part = 0.f;
    for (int j = q * 16; j < q * 16 + 16; j++) {
        float z = bc1[j];
#pragma unroll 4
        for (int k = 0; k < 128; k++) z += gs[gid][k] * Wc1[k * 64 + j];
        part += fmaxf(z, 0.f) * Wc2[j];
    }
    part += __shfl_down_sync(0xffffffffu, part, 2);
    part += __shfl_down_sync(0xffffffffu, part, 1);
    if (q == 0) out[gid] = 1.f / (1.f + expf(-(part + bc2[0])));
}

// ---------- launch ----------
extern "C" void kernel_launch(void* const* d_in, const int* in_sizes, int n_in,
                              void* d_out, int out_size) {
    const float* x   = (const float*)d_in[0];
    const int*   ei  = (const int*)d_in[1];
    const int*   bat = (const int*)d_in[2];
    const float* W1  = (const float*)d_in[3];
    const float* b1  = (const float*)d_in[4];
    const float* W2  = (const float*)d_in[5];
    const float* b2  = (const float*)d_in[6];
    const float* W3  = (const float*)d_in[7];
    const float* b3  = (const float*)d_in[8];
    const float* Wc1 = (const float*)d_in[9];
    const float* bc1 = (const float*)d_in[10];
    const float* Wc2 = (const float*)d_in[11];
    const float* bc2 = (const float*)d_in[12];
    float* out = (float*)d_out;

    const int* src = ei;
    const int* dst = ei + EE;

    cudaFuncSetAttribute(k_gemm_x, cudaFuncAttributeMaxDynamicSharedMemorySize, GT_SMEM);
    cudaFuncSetAttribute(k_fused, cudaFuncAttributeMaxDynamicSharedMemorySize, GT_SMEM);

    void *pA, *pB, *pWh;
    cudaGetSymbolAddress(&pA, g_bufA);
    cudaGetSymbolAddress(&pB, g_bufB);
    cudaGetSymbolAddress(&pWh, g_whi);
    __nv_bfloat16* bufA = (__nv_bfloat16*)pA;
    __nv_bfloat16* bufB = (__nv_bfloat16*)pB;
    __nv_bfloat16* whi = (__nv_bfloat16*)pWh;

    // fork a second stream for the CSR chain (created/destroyed per call; capture-safe)
    cudaStream_t s2;
    cudaStreamCreateWithFlags(&s2, cudaStreamNonBlocking);
    cudaEvent_t evF, evD, evJ;
    cudaEventCreateWithFlags(&evF, cudaEventDisableTiming);
    cudaEventCreateWithFlags(&evD, cudaEventDisableTiming);
    cudaEventCreateWithFlags(&evJ, cudaEventDisableTiming);

    cudaEventRecord(evF, 0);
    cudaStreamWaitEvent(s2, evF, 0);

    // stream 2: CSR build.  evD = dinv ready, evJ = full CSR ready.
    k_zdeg<<<(NN + 255) / 256, 256, 0, s2>>>();
    k_hist<<<(EE + 255) / 256, 256, 0, s2>>>(dst);
    k_scan1<<<SCAN_BLKS, 256, 0, s2>>>();
    k_scan3<<<SCAN_BLKS, 256, 0, s2>>>();
    cudaEventRecord(evD, s2);
    k_fill<<<(EE + 255) / 256, 256, 0, s2>>>(src, dst);
    cudaEventRecord(evJ, s2);

    // main stream: feature path
    const int gemm_grid = (NN + 127) / 128;
    const int agg_grid  = (NN + 7) / 8;

    k_init_misc<<<64, 256>>>();
    k_prepw<<<192, 256>>>(W1, W2, W3);

    cudaStreamWaitEvent(0, evD, 0);   // gemm_x epilogue reads g_dinv
    k_gemm_x<<<gemm_grid, 256, GT_SMEM>>>(x, whi, bufA);

    cudaStreamWaitEvent(0, evJ, 0);   // gathers need colsrc/rowptr

    k_fused<<<gemm_grid, 256, GT_SMEM>>>(bufA, b1, whi + HH * HH, bufB);      // agg1 + gemm2
    k_fused<<<gemm_grid, 256, GT_SMEM>>>(bufB, b2, whi + 2 * HH * HH, bufA);  // agg2 + gemm3
    k_agg<<<agg_grid, 256>>>(bufA, b3, bufB);                                  // agg3

    k_pool<<<(NN + POOL_NPB - 1) / POOL_NPB, 128>>>(bufB, bat);
    k_mlp<<<1, 256>>>(Wc1, bc1, Wc2, bc2, out);

    cudaEventDestroy(evF);
    cudaEventDestroy(evD);
    cudaEventDestroy(evJ);
    cudaStreamDestroy(s2);
}